// round 9
// baseline (speedup 1.0000x reference)
#include <cuda_runtime.h>
#include <cstdint>

#define NN 200000
#define EE 600000
#define GG 8192
#define HH 128

#define SCT 512
#define SCE 4
#define SCCHUNK (SCT * SCE)                      // 2048
#define SCB ((NN + SCCHUNK - 1) / SCCHUNK)       // 98

// Scratch (allocation-free rule: __device__ globals)
__device__ float  g_dinv[NN];
__device__ int    g_cnt_i[NN];
__device__ int    g_rowptr[NN + 1];
__device__ int    g_cursor[NN];
__device__ float2 g_cc[EE];                      // .x = col (as int bits), .y = coef
__device__ int    g_bsum[SCB];
__device__ float  g_h[(long long)NN * HH];
__device__ float  g_agg[(long long)NN * HH];
__device__ float  g_cntf[GG];

// ---------------- prep: zero counters + output ----------------
__global__ void k_prep(float* __restrict__ out) {
    int i = blockIdx.x * blockDim.x + threadIdx.x;
    if (i < NN) g_cnt_i[i] = 0;
    if (i < GG) g_cntf[i] = 0.0f;
    if (i < (GG * HH) / 4) ((float4*)out)[i] = make_float4(0.f, 0.f, 0.f, 0.f);
}

__global__ void k_count(const int* __restrict__ dst) {
    int e = blockIdx.x * blockDim.x + threadIdx.x;
    if (e < EE) atomicAdd(&g_cnt_i[__ldg(&dst[e])], 1);
}

__global__ void k_dinv() {
    int i = blockIdx.x * blockDim.x + threadIdx.x;
    if (i < NN) g_dinv[i] = rsqrtf(1.0f + (float)g_cnt_i[i]);
}

// ---------------- exclusive scan of g_cnt_i -> g_rowptr ----------------
__global__ void k_scan1() {
    __shared__ int wsum[SCT / 32];
    int t = threadIdx.x, b = blockIdx.x;
    int base = b * SCCHUNK + t * SCE;
    int s = 0;
    #pragma unroll
    for (int i = 0; i < SCE; i++) {
        int idx = base + i;
        if (idx < NN) s += g_cnt_i[idx];
    }
    int lane = t & 31, wid = t >> 5;
    #pragma unroll
    for (int o = 16; o > 0; o >>= 1) s += __shfl_down_sync(0xffffffffu, s, o);
    if (lane == 0) wsum[wid] = s;
    __syncthreads();
    if (wid == 0) {
        int v = (lane < SCT / 32) ? wsum[lane] : 0;
        #pragma unroll
        for (int o = 16; o > 0; o >>= 1) v += __shfl_down_sync(0xffffffffu, v, o);
        if (lane == 0) g_bsum[b] = v;
    }
}

__global__ void k_scan2() {
    if (threadIdx.x == 0) {
        int run = 0;
        for (int b = 0; b < SCB; b++) { int t = g_bsum[b]; g_bsum[b] = run; run += t; }
        g_rowptr[NN] = run;
    }
}

__global__ void k_scan3() {
    __shared__ int wsum[SCT / 32];
    __shared__ int wexcl[SCT / 32];
    int t = threadIdx.x, b = blockIdx.x;
    int base = b * SCCHUNK + t * SCE;
    int p[SCE];
    int run = 0;
    #pragma unroll
    for (int i = 0; i < SCE; i++) {
        int idx = base + i;
        int e = (idx < NN) ? g_cnt_i[idx] : 0;
        p[i] = run; run += e;
    }
    int lane = t & 31, wid = t >> 5;
    int v = run;
    #pragma unroll
    for (int o = 1; o < 32; o <<= 1) {
        int u = __shfl_up_sync(0xffffffffu, v, o);
        if (lane >= o) v += u;
    }
    int texcl = v - run;
    if (lane == 31) wsum[wid] = v;
    __syncthreads();
    if (wid == 0) {
        int w = (lane < SCT / 32) ? wsum[lane] : 0;
        int vv = w;
        #pragma unroll
        for (int o = 1; o < 32; o <<= 1) {
            int u = __shfl_up_sync(0xffffffffu, vv, o);
            if (lane >= o) vv += u;
        }
        if (lane < SCT / 32) wexcl[lane] = vv - w;
    }
    __syncthreads();
    int off = g_bsum[b] + wexcl[wid] + texcl;
    #pragma unroll
    for (int i = 0; i < SCE; i++) {
        int idx = base + i;
        if (idx < NN) { g_rowptr[idx] = off + p[i]; g_cursor[idx] = off + p[i]; }
    }
}

// ---------------- CSR fill (packed col+coef) ----------------
__global__ void k_fill(const int* __restrict__ src, const int* __restrict__ dst) {
    int e = blockIdx.x * blockDim.x + threadIdx.x;
    if (e >= EE) return;
    int s = __ldg(&src[e]), d = __ldg(&dst[e]);
    int pos = atomicAdd(&g_cursor[d], 1);
    g_cc[pos] = make_float2(__int_as_float(s), g_dinv[s] * g_dinv[d]);
}

__global__ void k_cnt(const int* __restrict__ batch) {
    int i = blockIdx.x * blockDim.x + threadIdx.x;
    if (i < NN) atomicAdd(&g_cntf[__ldg(&batch[i])], 1.0f);
}

// ---------------- aggregation (gather) ----------------
// 30-dim: warp per node. aggX[n] = x[n]*dinv^2 + sum_nbr x[s]*coef
// Output row stride 32 into g_agg; lanes 30/31 written as 0 (K=32 padding).
__global__ __launch_bounds__(256) void k_agg30(const float* __restrict__ x) {
    int n = (blockIdx.x * 256 + threadIdx.x) >> 5;
    if (n >= NN) return;
    int lane = threadIdx.x & 31;
    int beg = __ldg(&g_rowptr[n]), end = __ldg(&g_rowptr[n + 1]);
    float dv = g_dinv[n];
    float acc = 0.0f;
    if (lane < 30) acc = __ldg(&x[(long long)n * 30 + lane]) * dv * dv;
    #pragma unroll 4
    for (int j = beg; j < end; j++) {
        float2 cc = __ldg(&g_cc[j]);
        int s = __float_as_int(cc.x);
        if (lane < 30) acc += __ldg(&x[(long long)s * 30 + lane]) * cc.y;
    }
    g_agg[(long long)n * 32 + lane] = (lane < 30) ? acc : 0.0f;
}

// 128-dim: warp per node, lane handles one float4.
// g_agg[n] = g_h[n]*dinv^2 + sum_nbr g_h[s]*coef
__global__ __launch_bounds__(256) void k_agg128() {
    int n = (blockIdx.x * 256 + threadIdx.x) >> 5;
    if (n >= NN) return;
    int lane = threadIdx.x & 31;
    int beg = __ldg(&g_rowptr[n]), end = __ldg(&g_rowptr[n + 1]);
    float dv = g_dinv[n];
    const float4* h4 = (const float4*)g_h;
    float4 a = h4[(long long)n * 32 + lane];
    float d2 = dv * dv;
    float4 acc = make_float4(a.x * d2, a.y * d2, a.z * d2, a.w * d2);
    int j = beg;
    // unrolled-by-4 software pipeline: batch cc loads, then batch gathers
    for (; j + 4 <= end; j += 4) {
        float2 c0 = __ldg(&g_cc[j]);
        float2 c1 = __ldg(&g_cc[j + 1]);
        float2 c2 = __ldg(&g_cc[j + 2]);
        float2 c3 = __ldg(&g_cc[j + 3]);
        float4 v0 = __ldg(&h4[(long long)__float_as_int(c0.x) * 32 + lane]);
        float4 v1 = __ldg(&h4[(long long)__float_as_int(c1.x) * 32 + lane]);
        float4 v2 = __ldg(&h4[(long long)__float_as_int(c2.x) * 32 + lane]);
        float4 v3 = __ldg(&h4[(long long)__float_as_int(c3.x) * 32 + lane]);
        acc.x += v0.x * c0.y; acc.y += v0.y * c0.y; acc.z += v0.z * c0.y; acc.w += v0.w * c0.y;
        acc.x += v1.x * c1.y; acc.y += v1.y * c1.y; acc.z += v1.z * c1.y; acc.w += v1.w * c1.y;
        acc.x += v2.x * c2.y; acc.y += v2.y * c2.y; acc.z += v2.z * c2.y; acc.w += v2.w * c2.y;
        acc.x += v3.x * c3.y; acc.y += v3.y * c3.y; acc.z += v3.z * c3.y; acc.w += v3.w * c3.y;
    }
    for (; j < end; j++) {
        float2 cc = __ldg(&g_cc[j]);
        float4 v = __ldg(&h4[(long long)__float_as_int(cc.x) * 32 + lane]);
        acc.x += v.x * cc.y; acc.y += v.y * cc.y; acc.z += v.z * cc.y; acc.w += v.w * cc.y;
    }
    ((float4*)g_agg)[(long long)n * 32 + lane] = acc;
}

// ---------------- tf32 helpers ----------------
__device__ __forceinline__ float tf32r(float x) {
    uint32_t u;
    asm("cvt.rna.tf32.f32 %0, %1;" : "=r"(u) : "f"(x));
    return __uint_as_float(u);
}

__device__ __forceinline__ void mma_tf32(float* d, const uint32_t* a, const uint32_t* b) {
    asm volatile(
        "mma.sync.aligned.m16n8k8.row.col.f32.tf32.tf32.f32 "
        "{%0,%1,%2,%3}, {%4,%5,%6,%7}, {%8,%9}, {%0,%1,%2,%3};\n"
        : "+f"(d[0]), "+f"(d[1]), "+f"(d[2]), "+f"(d[3])
        : "r"(a[0]), "r"(a[1]), "r"(a[2]), "r"(a[3]),
          "r"(b[0]), "r"(b[1]));
}

// ---------------- GEMM (tf32 tensor cores) ----------------
// Reads g_agg (row stride LDA), computes relu(g_agg @ W + bias).
// MODE 0: store to g_h.  MODE 1: red.global.add into out[batch[row]*128+col].
// Block 256 thr = 8 warps (2 m x 4 n), block tile 128x128, warp tile 64x32.
template<int KREAL, int LDA, int MODE>
__global__ __launch_bounds__(256, 2) void k_gemm(
    const float* __restrict__ W, const float* __restrict__ bias,
    const int* __restrict__ batch, float* __restrict__ out)
{
    constexpr int KPAD = (KREAL + 31) & ~31;
    __shared__ float As[128][36];   // [m][k]
    __shared__ float Bs[32][132];   // [k][n]
    const int tid  = threadIdx.x;
    const int r0   = blockIdx.x * 128;
    const int lane = tid & 31;
    const int wp   = tid >> 5;
    const int wm   = wp >> 2;       // 0..1  (64 rows each)
    const int wn   = wp & 3;        // 0..3  (32 cols each)

    float acc[4][4][4];             // [mt][nt][frag]
    #pragma unroll
    for (int i = 0; i < 4; i++)
        #pragma unroll
        for (int j = 0; j < 4; j++)
            #pragma unroll
            for (int q = 0; q < 4; q++) acc[i][j][q] = 0.0f;

    for (int k0 = 0; k0 < KPAD; k0 += 32) {
        #pragma unroll
        for (int i = 0; i < 16; i++) {
            int f   = i * 256 + tid;
            int row = f >> 5, kk = f & 31;
            int gr  = r0 + row;
            float v = 0.0f;
            if (gr < NN) v = g_agg[(long long)gr * LDA + k0 + kk];
            As[row][kk] = tf32r(v);
        }
        #pragma unroll
        for (int i = 0; i < 16; i++) {
            int f  = i * 256 + tid;
            int kk = f >> 7, n = f & 127;
            int gk = k0 + kk;
            float v = (gk < KREAL) ? __ldg(&W[gk * 128 + n]) : 0.0f;
            Bs[kk][n] = tf32r(v);
        }
        __syncthreads();

        #pragma unroll
        for (int kq = 0; kq < 4; kq++) {
            const int kb = kq * 8;
            uint32_t afr[4][4];
            #pragma unroll
            for (int mt = 0; mt < 4; mt++) {
                int mr = wm * 64 + mt * 16 + (lane >> 2);
                int kc = kb + (lane & 3);
                afr[mt][0] = __float_as_uint(As[mr][kc]);
                afr[mt][1] = __float_as_uint(As[mr + 8][kc]);
                afr[mt][2] = __float_as_uint(As[mr][kc + 4]);
                afr[mt][3] = __float_as_uint(As[mr + 8][kc + 4]);
            }
            uint32_t bfr[4][2];
            #pragma unroll
            for (int nt = 0; nt < 4; nt++) {
                int nc = wn * 32 + nt * 8 + (lane >> 2);
                int kr = kb + (lane & 3);
                bfr[nt][0] = __float_as_uint(Bs[kr][nc]);
                bfr[nt][1] = __float_as_uint(Bs[kr + 4][nc]);
            }
            #pragma unroll
            for (int mt = 0; mt < 4; mt++)
                #pragma unroll
                for (int nt = 0; nt < 4; nt++)
                    mma_tf32(acc[mt][nt], afr[mt], bfr[nt]);
        }
        __syncthreads();
    }

    #pragma unroll
    for (int mt = 0; mt < 4; mt++) {
        int row  = r0 + wm * 64 + mt * 16 + (lane >> 2);
        int row2 = row + 8;
        #pragma unroll
        for (int nt = 0; nt < 4; nt++) {
            int col = wn * 32 + nt * 8 + (lane & 3) * 2;
            float b0 = __ldg(&bias[col]), b1 = __ldg(&bias[col + 1]);
            float v00 = fmaxf(acc[mt][nt][0] + b0, 0.0f);
            float v01 = fmaxf(acc[mt][nt][1] + b1, 0.0f);
            float v10 = fmaxf(acc[mt][nt][2] + b0, 0.0f);
            float v11 = fmaxf(acc[mt][nt][3] + b1, 0.0f);
            if (MODE == 0) {
                if (row  < NN) *(float2*)&g_h[(long long)row  * 128 + col] = make_float2(v00, v01);
                if (row2 < NN) *(float2*)&g_h[(long long)row2 * 128 + col] = make_float2(v10, v11);
            } else {
                if (row < NN) {
                    int g = __ldg(&batch[row]);
                    float* p = out + (long long)g * 128 + col;
                    asm volatile("red.global.add.v2.f32 [%0], {%1, %2};"
                                 :: "l"(p), "f"(v00), "f"(v01) : "memory");
                }
                if (row2 < NN) {
                    int g = __ldg(&batch[row2]);
                    float* p = out + (long long)g * 128 + col;
                    asm volatile("red.global.add.v2.f32 [%0], {%1, %2};"
                                 :: "l"(p), "f"(v10), "f"(v11) : "memory");
                }
            }
        }
    }
}

__global__ void k_div(float* __restrict__ out) {
    int i = blockIdx.x * blockDim.x + threadIdx.x;
    if (i < GG * HH) {
        float c = g_cntf[i >> 7];
        out[i] *= 1.0f / fmaxf(c, 1.0f);
    }
}

// ---------------- launch ----------------
extern "C" void kernel_launch(void* const* d_in, const int* in_sizes, int n_in,
                              void* d_out, int out_size)
{
    const float* x     = (const float*)d_in[0];   // [N, 30]
    const int*   ei    = (const int*)  d_in[1];   // [2, E]
    const int*   batch = (const int*)  d_in[2];   // [N]
    const float* W1    = (const float*)d_in[3];
    const float* b1    = (const float*)d_in[4];
    const float* W2    = (const float*)d_in[5];
    const float* b2    = (const float*)d_in[6];
    const float* W3    = (const float*)d_in[7];
    const float* b3    = (const float*)d_in[8];
    float* out = (float*)d_out;

    const int* src = ei;
    const int* dst = ei + EE;

    // prep (zero counters + out), CSR build (by dst) + dinv
    const int PREPN = (GG * HH) / 4;              // 262144 >= NN, GG
    k_prep <<<(PREPN + 255) / 256, 256>>>(out);
    k_count<<<(EE + 255) / 256, 256>>>(dst);
    k_dinv <<<(NN + 255) / 256, 256>>>();
    k_scan1<<<SCB, SCT>>>();
    k_scan2<<<1, 32>>>();
    k_scan3<<<SCB, SCT>>>();
    k_fill <<<(EE + 255) / 256, 256>>>(src, dst);
    k_cnt  <<<(NN + 255) / 256, 256>>>(batch);

    const int GB = (NN + 127) / 128;          // 1563 blocks
    const int AB = (NN * 32 + 255) / 256;     // 25000 warp-per-node blocks

    // Layer 1: agg in 30-dim input space, then h1 = relu(aggX @ W1 + b1)
    k_agg30<<<AB, 256>>>(x);
    k_gemm<30, 32, 0><<<GB, 256>>>(W1, b1, nullptr, nullptr);
    // Layer 2
    k_agg128<<<AB, 256>>>();
    k_gemm<128, 128, 0><<<GB, 256>>>(W2, b2, nullptr, nullptr);
    // Layer 3 (pool fused into epilogue)
    k_agg128<<<AB, 256>>>();
    k_gemm<128, 128, 1><<<GB, 256>>>(W3, b3, batch, out);

    k_div<<<(GG * HH + 255) / 256, 256>>>(out);
}

// round 12
// speedup vs baseline: 1.1131x; 1.1131x over previous
#include <cuda_runtime.h>
#include <cuda_fp16.h>
#include <cstdint>

#define NN 200000
#define EE 600000
#define GG 8192
#define HH 128

#define SCT 512
#define SCE 4
#define SCCHUNK (SCT * SCE)                      // 2048
#define SCB ((NN + SCCHUNK - 1) / SCCHUNK)       // 98

// Scratch (allocation-free rule: __device__ globals)
__device__ float  g_dinv[NN];
__device__ int    g_cnt_i[NN];
__device__ int    g_rowptr[NN + 1];
__device__ int    g_cursor[NN];
__device__ int    g_col[EE];
__device__ float  g_coef[EE];
__device__ int    g_bsum[SCB];
__device__ __half g_h[(long long)NN * HH];       // fp16 activations (gathered buffer)
__device__ float  g_agg[(long long)NN * HH];
__device__ float  g_cntf[GG];

// ---------------- degree / counts ----------------
__global__ void k_init() {
    int i = blockIdx.x * blockDim.x + threadIdx.x;
    if (i < NN) g_cnt_i[i] = 0;
}

__global__ void k_count(const int* __restrict__ dst) {
    int e = blockIdx.x * blockDim.x + threadIdx.x;
    if (e < EE) atomicAdd(&g_cnt_i[__ldg(&dst[e])], 1);
}

__global__ void k_dinv() {
    int i = blockIdx.x * blockDim.x + threadIdx.x;
    if (i < NN) g_dinv[i] = rsqrtf(1.0f + (float)g_cnt_i[i]);
}

// ---------------- exclusive scan of g_cnt_i -> g_rowptr ----------------
__global__ void k_scan1() {
    __shared__ int wsum[SCT / 32];
    int t = threadIdx.x, b = blockIdx.x;
    int base = b * SCCHUNK + t * SCE;
    int s = 0;
    #pragma unroll
    for (int i = 0; i < SCE; i++) {
        int idx = base + i;
        if (idx < NN) s += g_cnt_i[idx];
    }
    int lane = t & 31, wid = t >> 5;
    #pragma unroll
    for (int o = 16; o > 0; o >>= 1) s += __shfl_down_sync(0xffffffffu, s, o);
    if (lane == 0) wsum[wid] = s;
    __syncthreads();
    if (wid == 0) {
        int v = (lane < SCT / 32) ? wsum[lane] : 0;
        #pragma unroll
        for (int o = 16; o > 0; o >>= 1) v += __shfl_down_sync(0xffffffffu, v, o);
        if (lane == 0) g_bsum[b] = v;
    }
}

__global__ void k_scan2() {
    if (threadIdx.x == 0) {
        int run = 0;
        for (int b = 0; b < SCB; b++) { int t = g_bsum[b]; g_bsum[b] = run; run += t; }
        g_rowptr[NN] = run;
    }
}

__global__ void k_scan3() {
    __shared__ int wsum[SCT / 32];
    __shared__ int wexcl[SCT / 32];
    int t = threadIdx.x, b = blockIdx.x;
    int base = b * SCCHUNK + t * SCE;
    int p[SCE];
    int run = 0;
    #pragma unroll
    for (int i = 0; i < SCE; i++) {
        int idx = base + i;
        int e = (idx < NN) ? g_cnt_i[idx] : 0;
        p[i] = run; run += e;
    }
    int lane = t & 31, wid = t >> 5;
    int v = run;
    #pragma unroll
    for (int o = 1; o < 32; o <<= 1) {
        int u = __shfl_up_sync(0xffffffffu, v, o);
        if (lane >= o) v += u;
    }
    int texcl = v - run;
    if (lane == 31) wsum[wid] = v;
    __syncthreads();
    if (wid == 0) {
        int w = (lane < SCT / 32) ? wsum[lane] : 0;
        int vv = w;
        #pragma unroll
        for (int o = 1; o < 32; o <<= 1) {
            int u = __shfl_up_sync(0xffffffffu, vv, o);
            if (lane >= o) vv += u;
        }
        if (lane < SCT / 32) wexcl[lane] = vv - w;
    }
    __syncthreads();
    int off = g_bsum[b] + wexcl[wid] + texcl;
    #pragma unroll
    for (int i = 0; i < SCE; i++) {
        int idx = base + i;
        if (idx < NN) { g_rowptr[idx] = off + p[i]; g_cursor[idx] = off + p[i]; }
    }
}

// ---------------- CSR fill ----------------
__global__ void k_fill(const int* __restrict__ src, const int* __restrict__ dst) {
    int e = blockIdx.x * blockDim.x + threadIdx.x;
    if (e >= EE) return;
    int s = __ldg(&src[e]), d = __ldg(&dst[e]);
    int pos = atomicAdd(&g_cursor[d], 1);
    g_col[pos]  = s;
    g_coef[pos] = g_dinv[s] * g_dinv[d];
}

// ---------------- aggregation (gather) ----------------
// 30-dim: warp per node. aggX[n] = x[n]*dinv^2 + sum_nbr x[s]*coef
// Output row stride 32 into g_agg; lanes 30/31 written as 0 (K=32 padding).
__global__ __launch_bounds__(256) void k_agg30(const float* __restrict__ x) {
    int n = (blockIdx.x * 256 + threadIdx.x) >> 5;
    if (n >= NN) return;
    int lane = threadIdx.x & 31;
    int beg = __ldg(&g_rowptr[n]), end = __ldg(&g_rowptr[n + 1]);
    float dv = g_dinv[n];
    float acc = 0.0f;
    if (lane < 30) acc = __ldg(&x[(long long)n * 30 + lane]) * dv * dv;
    for (int j = beg; j < end; j++) {
        int s = __ldg(&g_col[j]);
        float c = __ldg(&g_coef[j]);
        if (lane < 30) acc += __ldg(&x[(long long)s * 30 + lane]) * c;
    }
    g_agg[(long long)n * 32 + lane] = (lane < 30) ? acc : 0.0f;
}

// 128-dim: warp per node; lane handles 4 halves (one 8-byte load) per row.
// g_agg[n] = g_h[n]*dinv^2 + sum_nbr g_h[s]*coef   (g_h is fp16)
__global__ __launch_bounds__(256) void k_agg128() {
    int n = (blockIdx.x * 256 + threadIdx.x) >> 5;
    if (n >= NN) return;
    int lane = threadIdx.x & 31;
    int beg = __ldg(&g_rowptr[n]), end = __ldg(&g_rowptr[n + 1]);
    float dv = g_dinv[n];
    const float2* h8 = (const float2*)g_h;   // 8 B = 4 halves; row = 32 float2
    float2 raw = __ldg(&h8[(long long)n * 32 + lane]);
    __half2 a0 = *reinterpret_cast<__half2*>(&raw.x);
    __half2 a1 = *reinterpret_cast<__half2*>(&raw.y);
    float2 f0 = __half22float2(a0), f1 = __half22float2(a1);
    float d2 = dv * dv;
    float4 acc = make_float4(f0.x * d2, f0.y * d2, f1.x * d2, f1.y * d2);
    for (int j = beg; j < end; j++) {
        int s = __ldg(&g_col[j]);
        float c = __ldg(&g_coef[j]);
        float2 rv = __ldg(&h8[(long long)s * 32 + lane]);
        __half2 v0 = *reinterpret_cast<__half2*>(&rv.x);
        __half2 v1 = *reinterpret_cast<__half2*>(&rv.y);
        float2 g0 = __half22float2(v0), g1 = __half22float2(v1);
        acc.x += g0.x * c; acc.y += g0.y * c; acc.z += g1.x * c; acc.w += g1.y * c;
    }
    ((float4*)g_agg)[(long long)n * 32 + lane] = acc;
}

// ---------------- tf32 helpers ----------------
__device__ __forceinline__ float tf32r(float x) {
    uint32_t u;
    asm("cvt.rna.tf32.f32 %0, %1;" : "=r"(u) : "f"(x));
    return __uint_as_float(u);
}

__device__ __forceinline__ void mma_tf32(float* d, const uint32_t* a, const uint32_t* b) {
    asm volatile(
        "mma.sync.aligned.m16n8k8.row.col.f32.tf32.tf32.f32 "
        "{%0,%1,%2,%3}, {%4,%5,%6,%7}, {%8,%9}, {%0,%1,%2,%3};\n"
        : "+f"(d[0]), "+f"(d[1]), "+f"(d[2]), "+f"(d[3])
        : "r"(a[0]), "r"(a[1]), "r"(a[2]), "r"(a[3]),
          "r"(b[0]), "r"(b[1]));
}

// ---------------- GEMM (tf32 tensor cores) ----------------
// Reads g_agg (row stride LDA), computes relu(g_agg @ W + bias).
// MODE 0: store fp16 to g_h.  MODE 1: red.global.add into out[batch[row]].
// Block 256 thr = 8 warps (2 m x 4 n), block tile 128x128, warp tile 64x32.
template<int KREAL, int LDA, int MODE>
__global__ __launch_bounds__(256, 2) void k_gemm(
    const float* __restrict__ W, const float* __restrict__ bias,
    const int* __restrict__ batch, float* __restrict__ out)
{
    constexpr int KPAD = (KREAL + 31) & ~31;
    __shared__ float As[128][36];   // [m][k]
    __shared__ float Bs[32][132];   // [k][n]
    const int tid  = threadIdx.x;
    const int r0   = blockIdx.x * 128;
    const int lane = tid & 31;
    const int wp   = tid >> 5;
    const int wm   = wp >> 2;       // 0..1  (64 rows each)
    const int wn   = wp & 3;        // 0..3  (32 cols each)

    float acc[4][4][4];             // [mt][nt][frag]
    #pragma unroll
    for (int i = 0; i < 4; i++)
        #pragma unroll
        for (int j = 0; j < 4; j++)
            #pragma unroll
            for (int q = 0; q < 4; q++) acc[i][j][q] = 0.0f;

    for (int k0 = 0; k0 < KPAD; k0 += 32) {
        #pragma unroll
        for (int i = 0; i < 16; i++) {
            int f   = i * 256 + tid;
            int row = f >> 5, kk = f & 31;
            int gr  = r0 + row;
            float v = 0.0f;
            if (gr < NN) v = g_agg[(long long)gr * LDA + k0 + kk];
            As[row][kk] = tf32r(v);
        }
        #pragma unroll
        for (int i = 0; i < 16; i++) {
            int f  = i * 256 + tid;
            int kk = f >> 7, n = f & 127;
            int gk = k0 + kk;
            float v = (gk < KREAL) ? __ldg(&W[gk * 128 + n]) : 0.0f;
            Bs[kk][n] = tf32r(v);
        }
        __syncthreads();

        #pragma unroll
        for (int kq = 0; kq < 4; kq++) {
            const int kb = kq * 8;
            uint32_t afr[4][4];
            #pragma unroll
            for (int mt = 0; mt < 4; mt++) {
                int mr = wm * 64 + mt * 16 + (lane >> 2);
                int kc = kb + (lane & 3);
                afr[mt][0] = __float_as_uint(As[mr][kc]);
                afr[mt][1] = __float_as_uint(As[mr + 8][kc]);
                afr[mt][2] = __float_as_uint(As[mr][kc + 4]);
                afr[mt][3] = __float_as_uint(As[mr + 8][kc + 4]);
            }
            uint32_t bfr[4][2];
            #pragma unroll
            for (int nt = 0; nt < 4; nt++) {
                int nc = wn * 32 + nt * 8 + (lane >> 2);
                int kr = kb + (lane & 3);
                bfr[nt][0] = __float_as_uint(Bs[kr][nc]);
                bfr[nt][1] = __float_as_uint(Bs[kr + 4][nc]);
            }
            #pragma unroll
            for (int mt = 0; mt < 4; mt++)
                #pragma unroll
                for (int nt = 0; nt < 4; nt++)
                    mma_tf32(acc[mt][nt], afr[mt], bfr[nt]);
        }
        __syncthreads();
    }

    #pragma unroll
    for (int mt = 0; mt < 4; mt++) {
        int row  = r0 + wm * 64 + mt * 16 + (lane >> 2);
        int row2 = row + 8;
        #pragma unroll
        for (int nt = 0; nt < 4; nt++) {
            int col = wn * 32 + nt * 8 + (lane & 3) * 2;
            float b0 = __ldg(&bias[col]), b1 = __ldg(&bias[col + 1]);
            float v00 = fmaxf(acc[mt][nt][0] + b0, 0.0f);
            float v01 = fmaxf(acc[mt][nt][1] + b1, 0.0f);
            float v10 = fmaxf(acc[mt][nt][2] + b0, 0.0f);
            float v11 = fmaxf(acc[mt][nt][3] + b1, 0.0f);
            if (MODE == 0) {
                if (row  < NN)
                    ((__half2*)g_h)[(long long)row  * 64 + (col >> 1)] = __floats2half2_rn(v00, v01);
                if (row2 < NN)
                    ((__half2*)g_h)[(long long)row2 * 64 + (col >> 1)] = __floats2half2_rn(v10, v11);
            } else {
                if (row < NN) {
                    int g = __ldg(&batch[row]);
                    float* p = out + (long long)g * 128 + col;
                    asm volatile("red.global.add.v2.f32 [%0], {%1, %2};"
                                 :: "l"(p), "f"(v00), "f"(v01) : "memory");
                }
                if (row2 < NN) {
                    int g = __ldg(&batch[row2]);
                    float* p = out + (long long)g * 128 + col;
                    asm volatile("red.global.add.v2.f32 [%0], {%1, %2};"
                                 :: "l"(p), "f"(v10), "f"(v11) : "memory");
                }
            }
        }
    }
}

// ---------------- pooling aux ----------------
__global__ void k_zero_out(float* __restrict__ out) {
    int i = blockIdx.x * blockDim.x + threadIdx.x;
    if (i < (GG * HH) / 4) ((float4*)out)[i] = make_float4(0.f, 0.f, 0.f, 0.f);
    if (i < GG) g_cntf[i] = 0.0f;
}

__global__ void k_cnt(const int* __restrict__ batch) {
    int i = blockIdx.x * blockDim.x + threadIdx.x;
    if (i < NN) atomicAdd(&g_cntf[__ldg(&batch[i])], 1.0f);
}

__global__ void k_div(float* __restrict__ out) {
    int i = blockIdx.x * blockDim.x + threadIdx.x;
    if (i < GG * HH) {
        float c = g_cntf[i >> 7];
        out[i] *= 1.0f / fmaxf(c, 1.0f);
    }
}

// ---------------- launch ----------------
extern "C" void kernel_launch(void* const* d_in, const int* in_sizes, int n_in,
                              void* d_out, int out_size)
{
    const float* x     = (const float*)d_in[0];   // [N, 30]
    const int*   ei    = (const int*)  d_in[1];   // [2, E]
    const int*   batch = (const int*)  d_in[2];   // [N]
    const float* W1    = (const float*)d_in[3];
    const float* b1    = (const float*)d_in[4];
    const float* W2    = (const float*)d_in[5];
    const float* b2    = (const float*)d_in[6];
    const float* W3    = (const float*)d_in[7];
    const float* b3    = (const float*)d_in[8];
    float* out = (float*)d_out;

    const int* src = ei;
    const int* dst = ei + EE;

    // CSR build (by dst) + dinv
    k_init <<<(NN + 255) / 256, 256>>>();
    k_count<<<(EE + 255) / 256, 256>>>(dst);
    k_dinv <<<(NN + 255) / 256, 256>>>();
    k_scan1<<<SCB, SCT>>>();
    k_scan2<<<1, 32>>>();
    k_scan3<<<SCB, SCT>>>();
    k_fill <<<(EE + 255) / 256, 256>>>(src, dst);

    // Pool prep (out must be zero before layer-3 RED epilogue)
    k_zero_out<<<(GG * HH / 4 + 255) / 256, 256>>>(out);
    k_cnt     <<<(NN + 255) / 256, 256>>>(batch);

    const int GB = (NN + 127) / 128;          // 1563 blocks
    const int AB = (NN * 32 + 255) / 256;     // 25000 warp-per-node blocks

    // Layer 1: agg in 30-dim input space, then h1 = relu(aggX @ W1 + b1)
    k_agg30<<<AB, 256>>>(x);
    k_gemm<30, 32, 0><<<GB, 256>>>(W1, b1, nullptr, nullptr);
    // Layer 2
    k_agg128<<<AB, 256>>>();
    k_gemm<128, 128, 0><<<GB, 256>>>(W2, b2, nullptr, nullptr);
    // Layer 3 (pool fused into epilogue)
    k_agg128<<<AB, 256>>>();
    k_gemm<128, 128, 1><<<GB, 256>>>(W3, b3, batch, out);

    k_div<<<(GG * HH + 255) / 256, 256>>>(out);
}

// round 13
// speedup vs baseline: 1.2421x; 1.1159x over previous
#include <cuda_runtime.h>
#include <cuda_fp16.h>
#include <cstdint>

#define NN 200000
#define EE 600000
#define GG 8192
#define HH 128

#define SCT 512
#define SCE 4
#define SCCHUNK (SCT * SCE)                      // 2048
#define SCB ((NN + SCCHUNK - 1) / SCCHUNK)       // 98

// Scratch (allocation-free rule: __device__ globals)
__device__ float  g_dinv[NN];
__device__ int    g_cnt_i[NN];
__device__ int    g_rowptr[NN + 1];
__device__ int    g_cursor[NN];
__device__ int    g_col[EE];
__device__ float  g_coef[EE];
__device__ int    g_bsum[SCB];
__device__ __half g_h[(long long)NN * HH];       // fp16 activations (gather source)
__device__ __half g_agg[(long long)NN * HH];     // fp16 aggregation output (GEMM A)
__device__ float  g_cntf[GG];

// ---------------- prep: zero counters + output ----------------
__global__ void k_prep(float* __restrict__ out) {
    int i = blockIdx.x * blockDim.x + threadIdx.x;
    if (i < NN) g_cnt_i[i] = 0;
    if (i < GG) g_cntf[i] = 0.0f;
    if (i < (GG * HH) / 4) ((float4*)out)[i] = make_float4(0.f, 0.f, 0.f, 0.f);
}

__global__ void k_count(const int* __restrict__ dst) {
    int e = blockIdx.x * blockDim.x + threadIdx.x;
    if (e < EE) atomicAdd(&g_cnt_i[__ldg(&dst[e])], 1);
}

__global__ void k_dinv() {
    int i = blockIdx.x * blockDim.x + threadIdx.x;
    if (i < NN) g_dinv[i] = rsqrtf(1.0f + (float)g_cnt_i[i]);
}

// ---------------- exclusive scan of g_cnt_i -> g_rowptr ----------------
__global__ void k_scan1() {
    __shared__ int wsum[SCT / 32];
    int t = threadIdx.x, b = blockIdx.x;
    int base = b * SCCHUNK + t * SCE;
    int s = 0;
    #pragma unroll
    for (int i = 0; i < SCE; i++) {
        int idx = base + i;
        if (idx < NN) s += g_cnt_i[idx];
    }
    int lane = t & 31, wid = t >> 5;
    #pragma unroll
    for (int o = 16; o > 0; o >>= 1) s += __shfl_down_sync(0xffffffffu, s, o);
    if (lane == 0) wsum[wid] = s;
    __syncthreads();
    if (wid == 0) {
        int v = (lane < SCT / 32) ? wsum[lane] : 0;
        #pragma unroll
        for (int o = 16; o > 0; o >>= 1) v += __shfl_down_sync(0xffffffffu, v, o);
        if (lane == 0) g_bsum[b] = v;
    }
}

__global__ void k_scan2() {
    if (threadIdx.x == 0) {
        int run = 0;
        for (int b = 0; b < SCB; b++) { int t = g_bsum[b]; g_bsum[b] = run; run += t; }
        g_rowptr[NN] = run;
    }
}

__global__ void k_scan3() {
    __shared__ int wsum[SCT / 32];
    __shared__ int wexcl[SCT / 32];
    int t = threadIdx.x, b = blockIdx.x;
    int base = b * SCCHUNK + t * SCE;
    int p[SCE];
    int run = 0;
    #pragma unroll
    for (int i = 0; i < SCE; i++) {
        int idx = base + i;
        int e = (idx < NN) ? g_cnt_i[idx] : 0;
        p[i] = run; run += e;
    }
    int lane = t & 31, wid = t >> 5;
    int v = run;
    #pragma unroll
    for (int o = 1; o < 32; o <<= 1) {
        int u = __shfl_up_sync(0xffffffffu, v, o);
        if (lane >= o) v += u;
    }
    int texcl = v - run;
    if (lane == 31) wsum[wid] = v;
    __syncthreads();
    if (wid == 0) {
        int w = (lane < SCT / 32) ? wsum[lane] : 0;
        int vv = w;
        #pragma unroll
        for (int o = 1; o < 32; o <<= 1) {
            int u = __shfl_up_sync(0xffffffffu, vv, o);
            if (lane >= o) vv += u;
        }
        if (lane < SCT / 32) wexcl[lane] = vv - w;
    }
    __syncthreads();
    int off = g_bsum[b] + wexcl[wid] + texcl;
    #pragma unroll
    for (int i = 0; i < SCE; i++) {
        int idx = base + i;
        if (idx < NN) { g_rowptr[idx] = off + p[i]; g_cursor[idx] = off + p[i]; }
    }
}

// ---------------- CSR fill ----------------
__global__ void k_fill(const int* __restrict__ src, const int* __restrict__ dst) {
    int e = blockIdx.x * blockDim.x + threadIdx.x;
    if (e >= EE) return;
    int s = __ldg(&src[e]), d = __ldg(&dst[e]);
    int pos = atomicAdd(&g_cursor[d], 1);
    g_col[pos]  = s;
    g_coef[pos] = g_dinv[s] * g_dinv[d];
}

__global__ void k_cnt(const int* __restrict__ batch) {
    int i = blockIdx.x * blockDim.x + threadIdx.x;
    if (i < NN) atomicAdd(&g_cntf[__ldg(&batch[i])], 1.0f);
}

// ---------------- aggregation (gather) ----------------
// 30-dim: warp per node. aggX[n] = x[n]*dinv^2 + sum_nbr x[s]*coef
// Output fp16, row stride 32; lanes 30/31 written as 0 (K=32 padding).
__global__ __launch_bounds__(256) void k_agg30(const float* __restrict__ x) {
    int n = (blockIdx.x * 256 + threadIdx.x) >> 5;
    if (n >= NN) return;
    int lane = threadIdx.x & 31;
    int beg = __ldg(&g_rowptr[n]), end = __ldg(&g_rowptr[n + 1]);
    float dv = g_dinv[n];
    float acc = 0.0f;
    if (lane < 30) acc = __ldg(&x[(long long)n * 30 + lane]) * dv * dv;
    for (int j = beg; j < end; j++) {
        int s = __ldg(&g_col[j]);
        float c = __ldg(&g_coef[j]);
        if (lane < 30) acc += __ldg(&x[(long long)s * 30 + lane]) * c;
    }
    g_agg[(long long)n * 32 + lane] = __float2half((lane < 30) ? acc : 0.0f);
}

// 128-dim: warp per node; lane handles 4 halves (one 8-byte load) per row.
// g_agg[n] = g_h[n]*dinv^2 + sum_nbr g_h[s]*coef   (fp16 in, fp32 acc, fp16 out)
__global__ __launch_bounds__(256) void k_agg128() {
    int n = (blockIdx.x * 256 + threadIdx.x) >> 5;
    if (n >= NN) return;
    int lane = threadIdx.x & 31;
    int beg = __ldg(&g_rowptr[n]), end = __ldg(&g_rowptr[n + 1]);
    float dv = g_dinv[n];
    const float2* h8 = (const float2*)g_h;   // 8 B = 4 halves; row = 32 float2
    float2 raw = __ldg(&h8[(long long)n * 32 + lane]);
    __half2 a0 = *reinterpret_cast<__half2*>(&raw.x);
    __half2 a1 = *reinterpret_cast<__half2*>(&raw.y);
    float2 f0 = __half22float2(a0), f1 = __half22float2(a1);
    float d2 = dv * dv;
    float4 acc = make_float4(f0.x * d2, f0.y * d2, f1.x * d2, f1.y * d2);
    for (int j = beg; j < end; j++) {
        int s = __ldg(&g_col[j]);
        float c = __ldg(&g_coef[j]);
        float2 rv = __ldg(&h8[(long long)s * 32 + lane]);
        __half2 v0 = *reinterpret_cast<__half2*>(&rv.x);
        __half2 v1 = *reinterpret_cast<__half2*>(&rv.y);
        float2 g0 = __half22float2(v0), g1 = __half22float2(v1);
        acc.x += g0.x * c; acc.y += g0.y * c; acc.z += g1.x * c; acc.w += g1.y * c;
    }
    __half2 o0 = __floats2half2_rn(acc.x, acc.y);
    __half2 o1 = __floats2half2_rn(acc.z, acc.w);
    float2 packed;
    *reinterpret_cast<__half2*>(&packed.x) = o0;
    *reinterpret_cast<__half2*>(&packed.y) = o1;
    ((float2*)g_agg)[(long long)n * 32 + lane] = packed;
}

// ---------------- tf32 helpers ----------------
__device__ __forceinline__ float tf32r(float x) {
    uint32_t u;
    asm("cvt.rna.tf32.f32 %0, %1;" : "=r"(u) : "f"(x));
    return __uint_as_float(u);
}

__device__ __forceinline__ void mma_tf32(float* d, const uint32_t* a, const uint32_t* b) {
    asm volatile(
        "mma.sync.aligned.m16n8k8.row.col.f32.tf32.tf32.f32 "
        "{%0,%1,%2,%3}, {%4,%5,%6,%7}, {%8,%9}, {%0,%1,%2,%3};\n"
        : "+f"(d[0]), "+f"(d[1]), "+f"(d[2]), "+f"(d[3])
        : "r"(a[0]), "r"(a[1]), "r"(a[2]), "r"(a[3]),
          "r"(b[0]), "r"(b[1]));
}

// ---------------- GEMM (tf32 tensor cores) ----------------
// Reads g_agg (fp16, row stride LDA halves), computes relu(g_agg @ W + bias).
// MODE 0: store fp16 to g_h.  MODE 1: red.global.add into out[batch[row]].
// Block 256 thr = 8 warps (2 m x 4 n), block tile 128x128, warp tile 64x32.
template<int KREAL, int LDA, int MODE>
__global__ __launch_bounds__(256, 2) void k_gemm(
    const float* __restrict__ W, const float* __restrict__ bias,
    const int* __restrict__ batch, float* __restrict__ out)
{
    constexpr int KPAD = (KREAL + 31) & ~31;
    __shared__ float As[128][36];   // [m][k]
    __shared__ float Bs[32][132];   // [k][n]
    const int tid  = threadIdx.x;
    const int r0   = blockIdx.x * 128;
    const int lane = tid & 31;
    const int wp   = tid >> 5;
    const int wm   = wp >> 2;       // 0..1  (64 rows each)
    const int wn   = wp & 3;        // 0..3  (32 cols each)

    float acc[4][4][4];             // [mt][nt][frag]
    #pragma unroll
    for (int i = 0; i < 4; i++)
        #pragma unroll
        for (int j = 0; j < 4; j++)
            #pragma unroll
            for (int q = 0; q < 4; q++) acc[i][j][q] = 0.0f;

    const __half2* A2 = (const __half2*)g_agg;

    for (int k0 = 0; k0 < KPAD; k0 += 32) {
        // A chunk: 128 rows x 16 half2 = 2048 half2; 8 iters x 256 threads
        #pragma unroll
        for (int i = 0; i < 8; i++) {
            int f   = i * 256 + tid;
            int row = f >> 4, u = f & 15;
            int gr  = r0 + row;
            float2 v = make_float2(0.0f, 0.0f);
            if (gr < NN) {
                __half2 hv = __ldg(&A2[(long long)gr * (LDA / 2) + (k0 >> 1) + u]);
                v = __half22float2(hv);
            }
            As[row][u * 2]     = tf32r(v.x);
            As[row][u * 2 + 1] = tf32r(v.y);
        }
        // W chunk (32x128), coalesced in n
        #pragma unroll
        for (int i = 0; i < 16; i++) {
            int f  = i * 256 + tid;
            int kk = f >> 7, n = f & 127;
            int gk = k0 + kk;
            float v = (gk < KREAL) ? __ldg(&W[gk * 128 + n]) : 0.0f;
            Bs[kk][n] = tf32r(v);
        }
        __syncthreads();

        #pragma unroll
        for (int kq = 0; kq < 4; kq++) {
            const int kb = kq * 8;
            uint32_t afr[4][4];
            #pragma unroll
            for (int mt = 0; mt < 4; mt++) {
                int mr = wm * 64 + mt * 16 + (lane >> 2);
                int kc = kb + (lane & 3);
                afr[mt][0] = __float_as_uint(As[mr][kc]);
                afr[mt][1] = __float_as_uint(As[mr + 8][kc]);
                afr[mt][2] = __float_as_uint(As[mr][kc + 4]);
                afr[mt][3] = __float_as_uint(As[mr + 8][kc + 4]);
            }
            uint32_t bfr[4][2];
            #pragma unroll
            for (int nt = 0; nt < 4; nt++) {
                int nc = wn * 32 + nt * 8 + (lane >> 2);
                int kr = kb + (lane & 3);
                bfr[nt][0] = __float_as_uint(Bs[kr][nc]);
                bfr[nt][1] = __float_as_uint(Bs[kr + 4][nc]);
            }
            #pragma unroll
            for (int mt = 0; mt < 4; mt++)
                #pragma unroll
                for (int nt = 0; nt < 4; nt++)
                    mma_tf32(acc[mt][nt], afr[mt], bfr[nt]);
        }
        __syncthreads();
    }

    #pragma unroll
    for (int mt = 0; mt < 4; mt++) {
        int row  = r0 + wm * 64 + mt * 16 + (lane >> 2);
        int row2 = row + 8;
        #pragma unroll
        for (int nt = 0; nt < 4; nt++) {
            int col = wn * 32 + nt * 8 + (lane & 3) * 2;
            float b0 = __ldg(&bias[col]), b1 = __ldg(&bias[col + 1]);
            float v00 = fmaxf(acc[mt][nt][0] + b0, 0.0f);
            float v01 = fmaxf(acc[mt][nt][1] + b1, 0.0f);
            float v10 = fmaxf(acc[mt][nt][2] + b0, 0.0f);
            float v11 = fmaxf(acc[mt][nt][3] + b1, 0.0f);
            if (MODE == 0) {
                if (row  < NN)
                    ((__half2*)g_h)[(long long)row  * 64 + (col >> 1)] = __floats2half2_rn(v00, v01);
                if (row2 < NN)
                    ((__half2*)g_h)[(long long)row2 * 64 + (col >> 1)] = __floats2half2_rn(v10, v11);
            } else {
                if (row < NN) {
                    int g = __ldg(&batch[row]);
                    float* p = out + (long long)g * 128 + col;
                    asm volatile("red.global.add.v2.f32 [%0], {%1, %2};"
                                 :: "l"(p), "f"(v00), "f"(v01) : "memory");
                }
                if (row2 < NN) {
                    int g = __ldg(&batch[row2]);
                    float* p = out + (long long)g * 128 + col;
                    asm volatile("red.global.add.v2.f32 [%0], {%1, %2};"
                                 :: "l"(p), "f"(v10), "f"(v11) : "memory");
                }
            }
        }
    }
}

__global__ void k_div(float* __restrict__ out) {
    int i = blockIdx.x * blockDim.x + threadIdx.x;
    if (i < GG * HH) {
        float c = g_cntf[i >> 7];
        out[i] *= 1.0f / fmaxf(c, 1.0f);
    }
}

// ---------------- launch ----------------
extern "C" void kernel_launch(void* const* d_in, const int* in_sizes, int n_in,
                              void* d_out, int out_size)
{
    const float* x     = (const float*)d_in[0];   // [N, 30]
    const int*   ei    = (const int*)  d_in[1];   // [2, E]
    const int*   batch = (const int*)  d_in[2];   // [N]
    const float* W1    = (const float*)d_in[3];
    const float* b1    = (const float*)d_in[4];
    const float* W2    = (const float*)d_in[5];
    const float* b2    = (const float*)d_in[6];
    const float* W3    = (const float*)d_in[7];
    const float* b3    = (const float*)d_in[8];
    float* out = (float*)d_out;

    const int* src = ei;
    const int* dst = ei + EE;

    // prep (zero cnt_i, cntf, out), CSR build (by dst) + dinv
    const int PREPN = (GG * HH) / 4;              // 262144 >= NN, GG
    k_prep <<<(PREPN + 255) / 256, 256>>>(out);
    k_count<<<(EE + 255) / 256, 256>>>(dst);
    k_dinv <<<(NN + 255) / 256, 256>>>();
    k_scan1<<<SCB, SCT>>>();
    k_scan2<<<1, 32>>>();
    k_scan3<<<SCB, SCT>>>();
    k_fill <<<(EE + 255) / 256, 256>>>(src, dst);
    k_cnt  <<<(NN + 255) / 256, 256>>>(batch);

    const int GB = (NN + 127) / 128;          // 1563 blocks
    const int AB = (NN * 32 + 255) / 256;     // 25000 warp-per-node blocks

    // Layer 1: agg in 30-dim input space, then h1 = relu(aggX @ W1 + b1)
    k_agg30<<<AB, 256>>>(x);
    k_gemm<30, 32, 0><<<GB, 256>>>(W1, b1, nullptr, nullptr);
    // Layer 2
    k_agg128<<<AB, 256>>>();
    k_gemm<128, 128, 0><<<GB, 256>>>(W2, b2, nullptr, nullptr);
    // Layer 3 (pool fused into epilogue)
    k_agg128<<<AB, 256>>>();
    k_gemm<128, 128, 1><<<GB, 256>>>(W3, b3, batch, out);

    k_div<<<(GG * HH + 255) / 256, 256>>>(out);
}

// round 14
// speedup vs baseline: 1.4031x; 1.1297x over previous
#include <cuda_runtime.h>
#include <cuda_fp16.h>
#include <cstdint>

#define NN 200000
#define EE 600000
#define GG 8192
#define HH 128

#define SCT 512
#define SCE 4
#define SCCHUNK (SCT * SCE)                      // 2048
#define SCB ((NN + SCCHUNK - 1) / SCCHUNK)       // 98

// Scratch (allocation-free rule: __device__ globals)
__device__ float  g_dinv[NN];
__device__ int    g_cnt_i[NN];
__device__ int    g_rowptr[NN + 1];
__device__ int    g_cursor[NN];
__device__ int    g_col[EE];
__device__ float  g_coef[EE];
__device__ int    g_bsum[SCB];
__device__ __half g_h[(long long)NN * HH];       // fp16 activations (gather source)
__device__ __half g_agg[(long long)NN * HH];     // fp16 aggregation output (GEMM A)
__device__ float  g_cntf[GG];

// ---------------- prep: zero counters + output ----------------
__global__ void k_prep(float* __restrict__ out) {
    int i = blockIdx.x * blockDim.x + threadIdx.x;
    if (i < NN) g_cnt_i[i] = 0;
    if (i < GG) g_cntf[i] = 0.0f;
    if (i < (GG * HH) / 4) ((float4*)out)[i] = make_float4(0.f, 0.f, 0.f, 0.f);
}

// edge-degree count + per-graph node count (folded)
__global__ void k_count(const int* __restrict__ dst, const int* __restrict__ batch) {
    int e = blockIdx.x * blockDim.x + threadIdx.x;
    if (e < EE) atomicAdd(&g_cnt_i[__ldg(&dst[e])], 1);
    if (e < NN) atomicAdd(&g_cntf[__ldg(&batch[e])], 1.0f);
}

__global__ void k_dinv() {
    int i = blockIdx.x * blockDim.x + threadIdx.x;
    if (i < NN) g_dinv[i] = rsqrtf(1.0f + (float)g_cnt_i[i]);
}

// ---------------- exclusive scan of g_cnt_i -> g_rowptr ----------------
__global__ void k_scan1() {
    __shared__ int wsum[SCT / 32];
    int t = threadIdx.x, b = blockIdx.x;
    int base = b * SCCHUNK + t * SCE;
    int s = 0;
    #pragma unroll
    for (int i = 0; i < SCE; i++) {
        int idx = base + i;
        if (idx < NN) s += g_cnt_i[idx];
    }
    int lane = t & 31, wid = t >> 5;
    #pragma unroll
    for (int o = 16; o > 0; o >>= 1) s += __shfl_down_sync(0xffffffffu, s, o);
    if (lane == 0) wsum[wid] = s;
    __syncthreads();
    if (wid == 0) {
        int v = (lane < SCT / 32) ? wsum[lane] : 0;
        #pragma unroll
        for (int o = 16; o > 0; o >>= 1) v += __shfl_down_sync(0xffffffffu, v, o);
        if (lane == 0) g_bsum[b] = v;
    }
}

__global__ void k_scan2() {
    if (threadIdx.x == 0) {
        int run = 0;
        for (int b = 0; b < SCB; b++) { int t = g_bsum[b]; g_bsum[b] = run; run += t; }
        g_rowptr[NN] = run;
    }
}

__global__ void k_scan3() {
    __shared__ int wsum[SCT / 32];
    __shared__ int wexcl[SCT / 32];
    int t = threadIdx.x, b = blockIdx.x;
    int base = b * SCCHUNK + t * SCE;
    int p[SCE];
    int run = 0;
    #pragma unroll
    for (int i = 0; i < SCE; i++) {
        int idx = base + i;
        int e = (idx < NN) ? g_cnt_i[idx] : 0;
        p[i] = run; run += e;
    }
    int lane = t & 31, wid = t >> 5;
    int v = run;
    #pragma unroll
    for (int o = 1; o < 32; o <<= 1) {
        int u = __shfl_up_sync(0xffffffffu, v, o);
        if (lane >= o) v += u;
    }
    int texcl = v - run;
    if (lane == 31) wsum[wid] = v;
    __syncthreads();
    if (wid == 0) {
        int w = (lane < SCT / 32) ? wsum[lane] : 0;
        int vv = w;
        #pragma unroll
        for (int o = 1; o < 32; o <<= 1) {
            int u = __shfl_up_sync(0xffffffffu, vv, o);
            if (lane >= o) vv += u;
        }
        if (lane < SCT / 32) wexcl[lane] = vv - w;
    }
    __syncthreads();
    int off = g_bsum[b] + wexcl[wid] + texcl;
    #pragma unroll
    for (int i = 0; i < SCE; i++) {
        int idx = base + i;
        if (idx < NN) { g_rowptr[idx] = off + p[i]; g_cursor[idx] = off + p[i]; }
    }
}

// ---------------- CSR fill ----------------
__global__ void k_fill(const int* __restrict__ src, const int* __restrict__ dst) {
    int e = blockIdx.x * blockDim.x + threadIdx.x;
    if (e >= EE) return;
    int s = __ldg(&src[e]), d = __ldg(&dst[e]);
    int pos = atomicAdd(&g_cursor[d], 1);
    g_col[pos]  = s;
    g_coef[pos] = g_dinv[s] * g_dinv[d];
}

// ---------------- aggregation (gather) ----------------
// 30-dim: warp per node. aggX[n] = x[n]*dinv^2 + sum_nbr x[s]*coef
// Output fp16, row stride 32; lanes 30/31 written as 0 (K=32 padding).
__global__ __launch_bounds__(256) void k_agg30(const float* __restrict__ x) {
    int n = (blockIdx.x * 256 + threadIdx.x) >> 5;
    if (n >= NN) return;
    int lane = threadIdx.x & 31;
    int beg = __ldg(&g_rowptr[n]), end = __ldg(&g_rowptr[n + 1]);
    float dv = g_dinv[n];
    float acc = 0.0f;
    if (lane < 30) acc = __ldg(&x[(long long)n * 30 + lane]) * dv * dv;
    for (int j = beg; j < end; j++) {
        int s = __ldg(&g_col[j]);
        float c = __ldg(&g_coef[j]);
        if (lane < 30) acc += __ldg(&x[(long long)s * 30 + lane]) * c;
    }
    g_agg[(long long)n * 32 + lane] = __float2half((lane < 30) ? acc : 0.0f);
}

// 128-dim: warp per node; lane handles 4 halves (one 8-byte load) per row.
// g_agg[n] = g_h[n]*dinv^2 + sum_nbr g_h[s]*coef   (fp16 in, fp32 acc, fp16 out)
__global__ __launch_bounds__(256) void k_agg128() {
    int n = (blockIdx.x * 256 + threadIdx.x) >> 5;
    if (n >= NN) return;
    int lane = threadIdx.x & 31;
    int beg = __ldg(&g_rowptr[n]), end = __ldg(&g_rowptr[n + 1]);
    float dv = g_dinv[n];
    const float2* h8 = (const float2*)g_h;   // 8 B = 4 halves; row = 32 float2
    float2 raw = __ldg(&h8[(long long)n * 32 + lane]);
    __half2 a0 = *reinterpret_cast<__half2*>(&raw.x);
    __half2 a1 = *reinterpret_cast<__half2*>(&raw.y);
    float2 f0 = __half22float2(a0), f1 = __half22float2(a1);
    float d2 = dv * dv;
    float4 acc = make_float4(f0.x * d2, f0.y * d2, f1.x * d2, f1.y * d2);
    for (int j = beg; j < end; j++) {
        int s = __ldg(&g_col[j]);
        float c = __ldg(&g_coef[j]);
        float2 rv = __ldg(&h8[(long long)s * 32 + lane]);
        __half2 v0 = *reinterpret_cast<__half2*>(&rv.x);
        __half2 v1 = *reinterpret_cast<__half2*>(&rv.y);
        float2 g0 = __half22float2(v0), g1 = __half22float2(v1);
        acc.x += g0.x * c; acc.y += g0.y * c; acc.z += g1.x * c; acc.w += g1.y * c;
    }
    __half2 o0 = __floats2half2_rn(acc.x, acc.y);
    __half2 o1 = __floats2half2_rn(acc.z, acc.w);
    float2 packed;
    *reinterpret_cast<__half2*>(&packed.x) = o0;
    *reinterpret_cast<__half2*>(&packed.y) = o1;
    ((float2*)g_agg)[(long long)n * 32 + lane] = packed;
}

// ---------------- fp16 MMA helper ----------------
__device__ __forceinline__ void mma_f16(float* d, const uint32_t* a, const uint32_t* b) {
    asm volatile(
        "mma.sync.aligned.m16n8k16.row.col.f32.f16.f16.f32 "
        "{%0,%1,%2,%3}, {%4,%5,%6,%7}, {%8,%9}, {%0,%1,%2,%3};\n"
        : "+f"(d[0]), "+f"(d[1]), "+f"(d[2]), "+f"(d[3])
        : "r"(a[0]), "r"(a[1]), "r"(a[2]), "r"(a[3]),
          "r"(b[0]), "r"(b[1]));
}

// ---------------- GEMM (fp16 tensor cores, fp32 accumulate) ----------------
// Reads g_agg (fp16, row stride LDA halves), computes relu(g_agg @ W + bias).
// MODE 0: store fp16 to g_h.  MODE 1: red.global.add into out[batch[row]].
// Block 256 thr = 8 warps (2 m x 4 n), block tile 128x128, warp tile 64x32.
// As: [m][k] half, pad 38 (19 words -> conflict-free). Bs: [n][k] half, pad 38.
template<int KREAL, int LDA, int MODE>
__global__ __launch_bounds__(256, 2) void k_gemm(
    const float* __restrict__ W, const float* __restrict__ bias,
    const int* __restrict__ batch, float* __restrict__ out)
{
    constexpr int KPAD = (KREAL + 31) & ~31;
    __shared__ __half As[128][38];   // [m][k_chunk]
    __shared__ __half Bs[128][38];   // [n][k_chunk]  (transposed W)
    const int tid  = threadIdx.x;
    const int r0   = blockIdx.x * 128;
    const int lane = tid & 31;
    const int wp   = tid >> 5;
    const int wm   = wp >> 2;       // 0..1  (64 rows each)
    const int wn   = wp & 3;        // 0..3  (32 cols each)

    float acc[4][4][4];             // [mt][nt][frag]
    #pragma unroll
    for (int i = 0; i < 4; i++)
        #pragma unroll
        for (int j = 0; j < 4; j++)
            #pragma unroll
            for (int q = 0; q < 4; q++) acc[i][j][q] = 0.0f;

    const __half2* A2 = (const __half2*)g_agg;

    for (int k0 = 0; k0 < KPAD; k0 += 32) {
        // A chunk: 128 rows x 16 half2; 8 iters x 256 threads, one half2 each
        #pragma unroll
        for (int i = 0; i < 8; i++) {
            int f   = i * 256 + tid;
            int row = f >> 4, u = f & 15;
            int gr  = r0 + row;
            __half2 hv = __floats2half2_rn(0.0f, 0.0f);
            if (gr < NN) hv = __ldg(&A2[(long long)gr * (LDA / 2) + (k0 >> 1) + u]);
            *reinterpret_cast<__half2*>(&As[row][u * 2]) = hv;
        }
        // W chunk (32 k x 128 n), stored transposed into Bs[n][k]
        #pragma unroll
        for (int i = 0; i < 16; i++) {
            int f  = i * 256 + tid;
            int kk = f >> 7, n = f & 127;
            int gk = k0 + kk;
            float v = (gk < KREAL) ? __ldg(&W[gk * 128 + n]) : 0.0f;
            Bs[n][kk] = __float2half(v);
        }
        __syncthreads();

        #pragma unroll
        for (int kq = 0; kq < 2; kq++) {
            const int kb = kq * 16;
            const int kc = kb + (lane & 3) * 2;
            uint32_t afr[4][4];
            #pragma unroll
            for (int mt = 0; mt < 4; mt++) {
                int mr = wm * 64 + mt * 16 + (lane >> 2);
                afr[mt][0] = *reinterpret_cast<const uint32_t*>(&As[mr][kc]);
                afr[mt][1] = *reinterpret_cast<const uint32_t*>(&As[mr + 8][kc]);
                afr[mt][2] = *reinterpret_cast<const uint32_t*>(&As[mr][kc + 8]);
                afr[mt][3] = *reinterpret_cast<const uint32_t*>(&As[mr + 8][kc + 8]);
            }
            uint32_t bfr[4][2];
            #pragma unroll
            for (int nt = 0; nt < 4; nt++) {
                int nc = wn * 32 + nt * 8 + (lane >> 2);
                bfr[nt][0] = *reinterpret_cast<const uint32_t*>(&Bs[nc][kc]);
                bfr[nt][1] = *reinterpret_cast<const uint32_t*>(&Bs[nc][kc + 8]);
            }
            #pragma unroll
            for (int mt = 0; mt < 4; mt++)
                #pragma unroll
                for (int nt = 0; nt < 4; nt++)
                    mma_f16(acc[mt][nt], afr[mt], bfr[nt]);
        }
        __syncthreads();
    }

    #pragma unroll
    for (int mt = 0; mt < 4; mt++) {
        int row  = r0 + wm * 64 + mt * 16 + (lane >> 2);
        int row2 = row + 8;
        #pragma unroll
        for (int nt = 0; nt < 4; nt++) {
            int col = wn * 32 + nt * 8 + (lane & 3) * 2;
            float b0 = __ldg(&bias[col]), b1 = __ldg(&bias[col + 1]);
            float v00 = fmaxf(acc[mt][nt][0] + b0, 0.0f);
            float v01 = fmaxf(acc[mt][nt][1] + b1, 0.0f);
            float v10 = fmaxf(acc[mt][nt][2] + b0, 0.0f);
            float v11 = fmaxf(acc[mt][nt][3] + b1, 0.0f);
            if (MODE == 0) {
                if (row  < NN)
                    ((__half2*)g_h)[(long long)row  * 64 + (col >> 1)] = __floats2half2_rn(v00, v01);
                if (row2 < NN)
                    ((__half2*)g_h)[(long long)row2 * 64 + (col >> 1)] = __floats2half2_rn(v10, v11);
            } else {
                if (row < NN) {
                    int g = __ldg(&batch[row]);
                    float* p = out + (long long)g * 128 + col;
                    asm volatile("red.global.add.v2.f32 [%0], {%1, %2};"
                                 :: "l"(p), "f"(v00), "f"(v01) : "memory");
                }
                if (row2 < NN) {
                    int g = __ldg(&batch[row2]);
                    float* p = out + (long long)g * 128 + col;
                    asm volatile("red.global.add.v2.f32 [%0], {%1, %2};"
                                 :: "l"(p), "f"(v10), "f"(v11) : "memory");
                }
            }
        }
    }
}

__global__ void k_div(float* __restrict__ out) {
    int i = blockIdx.x * blockDim.x + threadIdx.x;
    if (i < GG * HH) {
        float c = g_cntf[i >> 7];
        out[i] *= 1.0f / fmaxf(c, 1.0f);
    }
}

// ---------------- launch ----------------
extern "C" void kernel_launch(void* const* d_in, const int* in_sizes, int n_in,
                              void* d_out, int out_size)
{
    const float* x     = (const float*)d_in[0];   // [N, 30]
    const int*   ei    = (const int*)  d_in[1];   // [2, E]
    const int*   batch = (const int*)  d_in[2];   // [N]
    const float* W1    = (const float*)d_in[3];
    const float* b1    = (const float*)d_in[4];
    const float* W2    = (const float*)d_in[5];
    const float* b2    = (const float*)d_in[6];
    const float* W3    = (const float*)d_in[7];
    const float* b3    = (const float*)d_in[8];
    float* out = (float*)d_out;

    const int* src = ei;
    const int* dst = ei + EE;

    // prep (zero cnt_i, cntf, out), CSR build (by dst) + dinv
    const int PREPN = (GG * HH) / 4;              // 262144 >= NN, GG
    k_prep <<<(PREPN + 255) / 256, 256>>>(out);
    k_count<<<(EE + 255) / 256, 256>>>(dst, batch);
    k_dinv <<<(NN + 255) / 256, 256>>>();
    k_scan1<<<SCB, SCT>>>();
    k_scan2<<<1, 32>>>();
    k_scan3<<<SCB, SCT>>>();
    k_fill <<<(EE + 255) / 256, 256>>>(src, dst);

    const int GB = (NN + 127) / 128;          // 1563 blocks
    const int AB = (NN * 32 + 255) / 256;     // 25000 warp-per-node blocks

    // Layer 1: agg in 30-dim input space, then h1 = relu(aggX @ W1 + b1)
    k_agg30<<<AB, 256>>>(x);
    k_gemm<30, 32, 0><<<GB, 256>>>(W1, b1, nullptr, nullptr);
    // Layer 2
    k_agg128<<<AB, 256>>>();
    k_gemm<128, 128, 0><<<GB, 256>>>(W2, b2, nullptr, nullptr);
    // Layer 3 (pool fused into epilogue)
    k_agg128<<<AB, 256>>>();
    k_gemm<128, 128, 1><<<GB, 256>>>(W3, b3, batch, out);

    k_div<<<(GG * HH + 255) / 256, 256>>>(out);
}

// round 15
// speedup vs baseline: 1.5481x; 1.1033x over previous
#include <cuda_runtime.h>
#include <cuda_fp16.h>
#include <cstdint>

#define NN 200000
#define EE 600000
#define GG 8192
#define HH 128

#define SCT 512
#define SCE 4
#define SCCHUNK (SCT * SCE)                      // 2048
#define SCB ((NN + SCCHUNK - 1) / SCCHUNK)       // 98

// Scratch (allocation-free rule: __device__ globals)
__device__ float  g_dinv[NN];
__device__ int    g_cnt_i[NN];
__device__ int    g_rowptr[NN + 1];
__device__ int    g_cursor[NN];
__device__ int    g_col[EE];
__device__ float  g_coef[EE];
__device__ int    g_bsum[SCB];
__device__ __half g_h[(long long)NN * HH];       // fp16 activations (gather source)
__device__ __half g_agg[(long long)NN * HH];     // fp16 aggregation output (GEMM A)
__device__ __half g_wt[3 * 128 * 128];           // fp16 W^T per layer: [l][n][k]
__device__ float  g_cntf[GG];
__device__ float  g_cinv[GG];

// ---------------- W pre-convert: g_wt[l][n][k] = W_l[k][n] (fp16) ----------
__global__ void k_wconv(const float* __restrict__ W1, const float* __restrict__ W2,
                        const float* __restrict__ W3) {
    int i = blockIdx.x * blockDim.x + threadIdx.x;
    if (i >= 3 * 128 * 128) return;
    int l = i >> 14, rem = i & 16383;
    int n = rem >> 7, k = rem & 127;
    const float* W = (l == 0) ? W1 : (l == 1) ? W2 : W3;
    int K = (l == 0) ? 30 : 128;
    float v = (k < K) ? __ldg(&W[k * 128 + n]) : 0.0f;
    g_wt[i] = __float2half(v);
}

// ---------------- prep: zero counters + output ----------------
__global__ void k_prep(float* __restrict__ out) {
    int i = blockIdx.x * blockDim.x + threadIdx.x;
    if (i < NN) g_cnt_i[i] = 0;
    if (i < GG) g_cntf[i] = 0.0f;
    if (i < (GG * HH) / 4) ((float4*)out)[i] = make_float4(0.f, 0.f, 0.f, 0.f);
}

// edge-degree count + per-graph node count (folded)
__global__ void k_count(const int* __restrict__ dst, const int* __restrict__ batch) {
    int e = blockIdx.x * blockDim.x + threadIdx.x;
    if (e < EE) atomicAdd(&g_cnt_i[__ldg(&dst[e])], 1);
    if (e < NN) atomicAdd(&g_cntf[__ldg(&batch[e])], 1.0f);
}

__global__ void k_dinv() {
    int i = blockIdx.x * blockDim.x + threadIdx.x;
    if (i < NN) g_dinv[i] = rsqrtf(1.0f + (float)g_cnt_i[i]);
    if (i < GG) g_cinv[i] = 1.0f / fmaxf(g_cntf[i], 1.0f);
}

// ---------------- exclusive scan of g_cnt_i -> g_rowptr ----------------
__global__ void k_scan1() {
    __shared__ int wsum[SCT / 32];
    int t = threadIdx.x, b = blockIdx.x;
    int base = b * SCCHUNK + t * SCE;
    int s = 0;
    #pragma unroll
    for (int i = 0; i < SCE; i++) {
        int idx = base + i;
        if (idx < NN) s += g_cnt_i[idx];
    }
    int lane = t & 31, wid = t >> 5;
    #pragma unroll
    for (int o = 16; o > 0; o >>= 1) s += __shfl_down_sync(0xffffffffu, s, o);
    if (lane == 0) wsum[wid] = s;
    __syncthreads();
    if (wid == 0) {
        int v = (lane < SCT / 32) ? wsum[lane] : 0;
        #pragma unroll
        for (int o = 16; o > 0; o >>= 1) v += __shfl_down_sync(0xffffffffu, v, o);
        if (lane == 0) g_bsum[b] = v;
    }
}

__global__ void k_scan2() {
    if (threadIdx.x == 0) {
        int run = 0;
        for (int b = 0; b < SCB; b++) { int t = g_bsum[b]; g_bsum[b] = run; run += t; }
        g_rowptr[NN] = run;
    }
}

__global__ void k_scan3() {
    __shared__ int wsum[SCT / 32];
    __shared__ int wexcl[SCT / 32];
    int t = threadIdx.x, b = blockIdx.x;
    int base = b * SCCHUNK + t * SCE;
    int p[SCE];
    int run = 0;
    #pragma unroll
    for (int i = 0; i < SCE; i++) {
        int idx = base + i;
        int e = (idx < NN) ? g_cnt_i[idx] : 0;
        p[i] = run; run += e;
    }
    int lane = t & 31, wid = t >> 5;
    int v = run;
    #pragma unroll
    for (int o = 1; o < 32; o <<= 1) {
        int u = __shfl_up_sync(0xffffffffu, v, o);
        if (lane >= o) v += u;
    }
    int texcl = v - run;
    if (lane == 31) wsum[wid] = v;
    __syncthreads();
    if (wid == 0) {
        int w = (lane < SCT / 32) ? wsum[lane] : 0;
        int vv = w;
        #pragma unroll
        for (int o = 1; o < 32; o <<= 1) {
            int u = __shfl_up_sync(0xffffffffu, vv, o);
            if (lane >= o) vv += u;
        }
        if (lane < SCT / 32) wexcl[lane] = vv - w;
    }
    __syncthreads();
    int off = g_bsum[b] + wexcl[wid] + texcl;
    #pragma unroll
    for (int i = 0; i < SCE; i++) {
        int idx = base + i;
        if (idx < NN) { g_rowptr[idx] = off + p[i]; g_cursor[idx] = off + p[i]; }
    }
}

// ---------------- CSR fill ----------------
__global__ void k_fill(const int* __restrict__ src, const int* __restrict__ dst) {
    int e = blockIdx.x * blockDim.x + threadIdx.x;
    if (e >= EE) return;
    int s = __ldg(&src[e]), d = __ldg(&dst[e]);
    int pos = atomicAdd(&g_cursor[d], 1);
    g_col[pos]  = s;
    g_coef[pos] = g_dinv[s] * g_dinv[d];
}

// ---------------- aggregation (gather) ----------------
// 30-dim: warp per node. aggX[n] = x[n]*dinv^2 + sum_nbr x[s]*coef
// Output fp16, row stride 32; lanes 30/31 written as 0 (K=32 padding).
__global__ __launch_bounds__(256) void k_agg30(const float* __restrict__ x) {
    int n = (blockIdx.x * 256 + threadIdx.x) >> 5;
    if (n >= NN) return;
    int lane = threadIdx.x & 31;
    int beg = __ldg(&g_rowptr[n]), end = __ldg(&g_rowptr[n + 1]);
    float dv = g_dinv[n];
    float acc = 0.0f;
    if (lane < 30) acc = __ldg(&x[(long long)n * 30 + lane]) * dv * dv;
    for (int j = beg; j < end; j++) {
        int s = __ldg(&g_col[j]);
        float c = __ldg(&g_coef[j]);
        if (lane < 30) acc += __ldg(&x[(long long)s * 30 + lane]) * c;
    }
    g_agg[(long long)n * 32 + lane] = __float2half((lane < 30) ? acc : 0.0f);
}

// 128-dim: warp per node; lane handles 4 halves (one 8-byte load) per row.
// g_agg[n] = g_h[n]*dinv^2 + sum_nbr g_h[s]*coef   (fp16 in, fp32 acc, fp16 out)
__global__ __launch_bounds__(256) void k_agg128() {
    int n = (blockIdx.x * 256 + threadIdx.x) >> 5;
    if (n >= NN) return;
    int lane = threadIdx.x & 31;
    int beg = __ldg(&g_rowptr[n]), end = __ldg(&g_rowptr[n + 1]);
    float dv = g_dinv[n];
    const float2* h8 = (const float2*)g_h;   // 8 B = 4 halves; row = 32 float2
    float2 raw = __ldg(&h8[(long long)n * 32 + lane]);
    __half2 a0 = *reinterpret_cast<__half2*>(&raw.x);
    __half2 a1 = *reinterpret_cast<__half2*>(&raw.y);
    float2 f0 = __half22float2(a0), f1 = __half22float2(a1);
    float d2 = dv * dv;
    float4 acc = make_float4(f0.x * d2, f0.y * d2, f1.x * d2, f1.y * d2);
    for (int j = beg; j < end; j++) {
        int s = __ldg(&g_col[j]);
        float c = __ldg(&g_coef[j]);
        float2 rv = __ldg(&h8[(long long)s * 32 + lane]);
        __half2 v0 = *reinterpret_cast<__half2*>(&rv.x);
        __half2 v1 = *reinterpret_cast<__half2*>(&rv.y);
        float2 g0 = __half22float2(v0), g1 = __half22float2(v1);
        acc.x += g0.x * c; acc.y += g0.y * c; acc.z += g1.x * c; acc.w += g1.y * c;
    }
    __half2 o0 = __floats2half2_rn(acc.x, acc.y);
    __half2 o1 = __floats2half2_rn(acc.z, acc.w);
    float2 packed;
    *reinterpret_cast<__half2*>(&packed.x) = o0;
    *reinterpret_cast<__half2*>(&packed.y) = o1;
    ((float2*)g_agg)[(long long)n * 32 + lane] = packed;
}

// ---------------- fp16 MMA helper ----------------
__device__ __forceinline__ void mma_f16(float* d, const uint32_t* a, const uint32_t* b) {
    asm volatile(
        "mma.sync.aligned.m16n8k16.row.col.f32.f16.f16.f32 "
        "{%0,%1,%2,%3}, {%4,%5,%6,%7}, {%8,%9}, {%0,%1,%2,%3};\n"
        : "+f"(d[0]), "+f"(d[1]), "+f"(d[2]), "+f"(d[3])
        : "r"(a[0]), "r"(a[1]), "r"(a[2]), "r"(a[3]),
          "r"(b[0]), "r"(b[1]));
}

// ---------------- GEMM (fp16 tensor cores, fp32 accumulate) ----------------
// A = g_agg (fp16, row stride LDA halves); B = g_wt[WL] (fp16 [n][k], stride 128).
// Computes relu(A @ W + bias).
// MODE 0: store fp16 to g_h.  MODE 1: red.global.add of v*cinv into out[batch].
// Block 256 thr = 8 warps (2 m x 4 n), block tile 128x128, warp tile 64x32.
// As/Bs: [row][40] half (80 B rows, 16B-aligned; 20-word stride -> conflict-free).
template<int KREAL, int LDA, int WL, int MODE>
__global__ __launch_bounds__(256, 2) void k_gemm(
    const float* __restrict__ bias, const int* __restrict__ batch,
    float* __restrict__ out)
{
    constexpr int KPAD = (KREAL + 31) & ~31;
    __shared__ __align__(16) __half As[128][40];   // [m][k_chunk]
    __shared__ __align__(16) __half Bs[128][40];   // [n][k_chunk]
    const int tid  = threadIdx.x;
    const int r0   = blockIdx.x * 128;
    const int lane = tid & 31;
    const int wp   = tid >> 5;
    const int wm   = wp >> 2;       // 0..1  (64 rows each)
    const int wn   = wp & 3;        // 0..3  (32 cols each)

    float acc[4][4][4];             // [mt][nt][frag]
    #pragma unroll
    for (int i = 0; i < 4; i++)
        #pragma unroll
        for (int j = 0; j < 4; j++)
            #pragma unroll
            for (int q = 0; q < 4; q++) acc[i][j][q] = 0.0f;

    const uint4* A4 = (const uint4*)g_agg;               // 8 halves per uint4
    const uint4* B4 = (const uint4*)(g_wt + (WL << 14)); // row stride 16 uint4

    for (int k0 = 0; k0 < KPAD; k0 += 32) {
        // A chunk: 128 rows x 4 uint4 = 512; 2 iters x 256 threads
        #pragma unroll
        for (int i = 0; i < 2; i++) {
            int f   = i * 256 + tid;
            int row = f >> 2, u = f & 3;
            int gr  = r0 + row;
            uint4 v = make_uint4(0, 0, 0, 0);
            if (gr < NN) v = __ldg(&A4[(long long)gr * (LDA / 8) + (k0 >> 3) + u]);
            *reinterpret_cast<uint4*>(&As[row][u * 8]) = v;
        }
        // B chunk: 128 n-rows x 4 uint4
        #pragma unroll
        for (int i = 0; i < 2; i++) {
            int f = i * 256 + tid;
            int n = f >> 2, u = f & 3;
            uint4 v = __ldg(&B4[n * 16 + (k0 >> 3) + u]);
            *reinterpret_cast<uint4*>(&Bs[n][u * 8]) = v;
        }
        __syncthreads();

        #pragma unroll
        for (int kq = 0; kq < 2; kq++) {
            const int kc = kq * 16 + (lane & 3) * 2;
            uint32_t afr[4][4];
            #pragma unroll
            for (int mt = 0; mt < 4; mt++) {
                int mr = wm * 64 + mt * 16 + (lane >> 2);
                afr[mt][0] = *reinterpret_cast<const uint32_t*>(&As[mr][kc]);
                afr[mt][1] = *reinterpret_cast<const uint32_t*>(&As[mr + 8][kc]);
                afr[mt][2] = *reinterpret_cast<const uint32_t*>(&As[mr][kc + 8]);
                afr[mt][3] = *reinterpret_cast<const uint32_t*>(&As[mr + 8][kc + 8]);
            }
            uint32_t bfr[4][2];
            #pragma unroll
            for (int nt = 0; nt < 4; nt++) {
                int nc = wn * 32 + nt * 8 + (lane >> 2);
                bfr[nt][0] = *reinterpret_cast<const uint32_t*>(&Bs[nc][kc]);
                bfr[nt][1] = *reinterpret_cast<const uint32_t*>(&Bs[nc][kc + 8]);
            }
            #pragma unroll
            for (int mt = 0; mt < 4; mt++)
                #pragma unroll
                for (int nt = 0; nt < 4; nt++)
                    mma_f16(acc[mt][nt], afr[mt], bfr[nt]);
        }
        __syncthreads();
    }

    #pragma unroll
    for (int mt = 0; mt < 4; mt++) {
        int row  = r0 + wm * 64 + mt * 16 + (lane >> 2);
        int row2 = row + 8;
        #pragma unroll
        for (int nt = 0; nt < 4; nt++) {
            int col = wn * 32 + nt * 8 + (lane & 3) * 2;
            float b0 = __ldg(&bias[col]), b1 = __ldg(&bias[col + 1]);
            float v00 = fmaxf(acc[mt][nt][0] + b0, 0.0f);
            float v01 = fmaxf(acc[mt][nt][1] + b1, 0.0f);
            float v10 = fmaxf(acc[mt][nt][2] + b0, 0.0f);
            float v11 = fmaxf(acc[mt][nt][3] + b1, 0.0f);
            if (MODE == 0) {
                if (row  < NN)
                    ((__half2*)g_h)[(long long)row  * 64 + (col >> 1)] = __floats2half2_rn(v00, v01);
                if (row2 < NN)
                    ((__half2*)g_h)[(long long)row2 * 64 + (col >> 1)] = __floats2half2_rn(v10, v11);
            } else {
                if (row < NN) {
                    int g = __ldg(&batch[row]);
                    float ci = g_cinv[g];
                    float* p = out + (long long)g * 128 + col;
                    asm volatile("red.global.add.v2.f32 [%0], {%1, %2};"
                                 :: "l"(p), "f"(v00 * ci), "f"(v01 * ci) : "memory");
                }
                if (row2 < NN) {
                    int g = __ldg(&batch[row2]);
                    float ci = g_cinv[g];
                    float* p = out + (long long)g * 128 + col;
                    asm volatile("red.global.add.v2.f32 [%0], {%1, %2};"
                                 :: "l"(p), "f"(v10 * ci), "f"(v11 * ci) : "memory");
                }
            }
        }
    }
}

// ---------------- launch ----------------
extern "C" void kernel_launch(void* const* d_in, const int* in_sizes, int n_in,
                              void* d_out, int out_size)
{
    const float* x     = (const float*)d_in[0];   // [N, 30]
    const int*   ei    = (const int*)  d_in[1];   // [2, E]
    const int*   batch = (const int*)  d_in[2];   // [N]
    const float* W1    = (const float*)d_in[3];
    const float* b1    = (const float*)d_in[4];
    const float* W2    = (const float*)d_in[5];
    const float* b2    = (const float*)d_in[6];
    const float* W3    = (const float*)d_in[7];
    const float* b3    = (const float*)d_in[8];
    float* out = (float*)d_out;

    const int* src = ei;
    const int* dst = ei + EE;

    // W pre-convert (independent of graph work), prep, CSR build + dinv/cinv
    k_wconv<<<(3 * 128 * 128 + 255) / 256, 256>>>(W1, W2, W3);
    const int PREPN = (GG * HH) / 4;              // 262144 >= NN, GG
    k_prep <<<(PREPN + 255) / 256, 256>>>(out);
    k_count<<<(EE + 255) / 256, 256>>>(dst, batch);
    k_dinv <<<(NN + 255) / 256, 256>>>();
    k_scan1<<<SCB, SCT>>>();
    k_scan2<<<1, 32>>>();
    k_scan3<<<SCB, SCT>>>();
    k_fill <<<(EE + 255) / 256, 256>>>(src, dst);

    const int GB = (NN + 127) / 128;          // 1563 blocks
    const int AB = (NN * 32 + 255) / 256;     // 25000 warp-per-node blocks

    // Layer 1: agg in 30-dim input space, then h1 = relu(aggX @ W1 + b1)
    k_agg30<<<AB, 256>>>(x);
    k_gemm<30, 32, 0, 0><<<GB, 256>>>(b1, nullptr, nullptr);
    // Layer 2
    k_agg128<<<AB, 256>>>();
    k_gemm<128, 128, 1, 0><<<GB, 256>>>(b2, nullptr, nullptr);
    // Layer 3 (pool + mean fused into epilogue)
    k_agg128<<<AB, 256>>>();
    k_gemm<128, 128, 2, 1><<<GB, 256>>>(b3, batch, out);
}